// round 1
// baseline (speedup 1.0000x reference)
#include <cuda_runtime.h>
#include <cuda_bf16.h>

// ---------------------------------------------------------------------------
// ContrastivePatchLoss fused kernel set.
// B=8, C=256, H=W=64, PATCH=8 -> 512 patches x 64 rows x 256 ch.
// Bank: L=32 -> 2048 x 256. TEMP=0.5, EPS=1e-5.
// ---------------------------------------------------------------------------

#define NPATCH      512
#define ROWS_TOT    32768          // 512*64
#define CDIM        256
#define NBANK       2048
#define INV_TEMP    2.0f
#define EPSV        1e-5f
#define NEG_HUGE    (-1e30f)

// scratch (device globals; no allocation allowed)
__device__ __nv_bfloat16 g_A[ROWS_TOT * CDIM];       // anchors bf16, row-major [32768][256]
__device__ __nv_bfloat16 g_negB[NBANK * CDIM];       // neg bank bf16 [2048][256]
__device__ __nv_bfloat16 g_posB[NBANK * CDIM];       // pos bank bf16 [2048][256]
__device__ float         g_pos_sim[ROWS_TOT];        // fp32 pos logits
__device__ int           g_use_pos[NPATCH];
__device__ float         g_part[256];                // per-block loss partials

// ---------------------------------------------------------------------------
// helpers
// ---------------------------------------------------------------------------
__device__ __forceinline__ unsigned smem_u32(const void* p) {
    return (unsigned)__cvta_generic_to_shared(p);
}
__device__ __forceinline__ void ldsm4(unsigned& r0, unsigned& r1, unsigned& r2, unsigned& r3,
                                      unsigned addr) {
    asm volatile("ldmatrix.sync.aligned.m8n8.x4.shared.b16 {%0,%1,%2,%3}, [%4];\n"
                 : "=r"(r0), "=r"(r1), "=r"(r2), "=r"(r3) : "r"(addr));
}
__device__ __forceinline__ void mma_bf16(float* c, unsigned a0, unsigned a1, unsigned a2,
                                         unsigned a3, unsigned b0, unsigned b1) {
    asm volatile("mma.sync.aligned.m16n8k16.row.col.f32.bf16.bf16.f32 "
                 "{%0,%1,%2,%3},{%4,%5,%6,%7},{%8,%9},{%0,%1,%2,%3};\n"
                 : "+f"(c[0]), "+f"(c[1]), "+f"(c[2]), "+f"(c[3])
                 : "r"(a0), "r"(a1), "r"(a2), "r"(a3), "r"(b0), "r"(b1));
}

// ---------------------------------------------------------------------------
// 1) label patch means -> use_pos flags.  grid 512, block 256
// ---------------------------------------------------------------------------
__global__ void label_kernel(const float* __restrict__ lab) {
    __shared__ float sred[8];
    const int p = blockIdx.x, t = threadIdx.x;
    const int b = p >> 6, j = (p >> 3) & 7, k = p & 7;
    const float* base = lab + (size_t)b * 65536 + (size_t)j * 32 * 256 + k * 32;
    float sum = 0.f;
#pragma unroll
    for (int it = 0; it < 4; ++it) {
        int u = t + 256 * it;
        int y = u >> 5, x = u & 31;
        sum += base[y * 256 + x];
    }
#pragma unroll
    for (int o = 16; o; o >>= 1) sum += __shfl_xor_sync(~0u, sum, o);
    if ((t & 31) == 0) sred[t >> 5] = sum;
    __syncthreads();
    if (t == 0) {
        float s2 = 0.f;
#pragma unroll
        for (int i = 0; i < 8; ++i) s2 += sred[i];
        g_use_pos[p] = (s2 * (1.f / 1024.f) < 0.1f) ? 1 : 0;
    }
}

// ---------------------------------------------------------------------------
// 2) banks [32,256,8,8] f32 -> [2048,256] bf16 (m = l*64 + y*8+x, col = c)
//    grid 64 (bank = blk>>5, l = blk&31), block 256
// ---------------------------------------------------------------------------
__global__ void convert_bank_kernel(const float* __restrict__ neg, const float* __restrict__ pos) {
    __shared__ __nv_bfloat16 sT[256][66];
    const int blk = blockIdx.x, t = threadIdx.x;
    const int bank = blk >> 5, l = blk & 31;
    const float* src = (bank ? pos : neg) + (size_t)l * 16384;
#pragma unroll 4
    for (int it = 0; it < 64; ++it) {
        int u = t + 256 * it;
        int c = u >> 6, s = u & 63;
        sT[c][s] = __float2bfloat16(src[c * 64 + s]);
    }
    __syncthreads();
    __nv_bfloat16* dst = (bank ? g_posB : g_negB) + (size_t)l * 64 * 256;
    unsigned* dst32 = (unsigned*)dst;
#pragma unroll 4
    for (int it = 0; it < 32; ++it) {
        int u = t + 256 * it;
        int s = u >> 7, cc = u & 127;
        unsigned lo = __bfloat16_as_ushort(sT[2 * cc][s]);
        unsigned hi = __bfloat16_as_ushort(sT[2 * cc + 1][s]);
        dst32[s * 128 + cc] = (hi << 16) | lo;
    }
}

// ---------------------------------------------------------------------------
// 3) anchors: main_out -> g_A bf16 [patch*64 + n][c], plus fp32 pos_sim with ema.
//    grid 512 (one patch), block 256
// ---------------------------------------------------------------------------
__global__ void convert_anchor_kernel(const float* __restrict__ mainp,
                                      const float* __restrict__ emap) {
    __shared__ __nv_bfloat16 sA[64][258];
    __shared__ float sdot[4][64];
    const int p = blockIdx.x, t = threadIdx.x;
    const int b = p >> 6, j = (p >> 3) & 7, k = p & 7;
    const int n = t & 63, y = n >> 3, x = n & 7;
    const size_t base = (size_t)b * 1048576 + (size_t)(j * 8 + y) * 64 + (k * 8 + x);
    float dot = 0.f;
#pragma unroll 8
    for (int it = 0; it < 64; ++it) {
        int c = (t >> 6) + 4 * it;
        size_t g = base + (size_t)c * 4096;
        float mv = mainp[g];
        float ev = emap[g];
        dot += mv * ev;
        sA[n][c] = __float2bfloat16(mv);
    }
    sdot[t >> 6][n] = dot;
    __syncthreads();
    if (t < 64) {
        float d = sdot[0][t] + sdot[1][t] + sdot[2][t] + sdot[3][t];
        g_pos_sim[p * 64 + t] = d * INV_TEMP;
    }
    unsigned* A32 = (unsigned*)g_A;
#pragma unroll 4
    for (int it = 0; it < 32; ++it) {
        int u = t + 256 * it;
        int n2 = u >> 7, cc = u & 127;
        unsigned v = *(const unsigned*)((const char*)&sA[0][0] + (size_t)n2 * 516 + cc * 4);
        A32[((size_t)p * 64 + n2) * 128 + cc] = v;
    }
}

// ---------------------------------------------------------------------------
// 4) fused GEMM + online softmax.
//    block = 2 patches (128 rows), grid 256.  N chunks of 64, K=256 resident.
//    warps: w in 0..7 -> rows 16w..16w+15, full 64-col chunk.
// smem: sA bf16 [128][264] (67584B) + sB bf16 [2 buf][2 half][64][72] (36864B)
// ---------------------------------------------------------------------------
#define SA_BYTES 67584
#define SB_HALF_ELEM 4608        // 64*72
#define SMEM_MAIN (SA_BYTES + 36864)

__global__ __launch_bounds__(256, 2) void gemm_softmax_kernel() {
    extern __shared__ __align__(16) unsigned char smem[];
    __nv_bfloat16* sA = (__nv_bfloat16*)smem;
    __nv_bfloat16* sB = (__nv_bfloat16*)(smem + SA_BYTES);
    __shared__ float red[8];

    const int t = threadIdx.x;
    const int q = blockIdx.x;
    const int w = t >> 5, lane = t & 31;

    const int f0 = g_use_pos[2 * q];
    const int f1 = g_use_pos[2 * q + 1];
    const int diff = (f0 != f1);
    const uint4* bank0 = (const uint4*)(f0 ? g_posB : g_negB);
    const uint4* bank1 = (const uint4*)(f1 ? g_posB : g_negB);
    const int myhalf = diff ? (w >> 2) : 0;

    // ---- load A tile (128 x 256 bf16) ----
    const uint4* Ag = (const uint4*)g_A + (size_t)q * 128 * 32;
#pragma unroll
    for (int i = 0; i < 16; ++i) {
        int u = t + 256 * i;
        int r = u >> 5, c16 = u & 31;
        *(uint4*)((char*)sA + r * 528 + c16 * 16) = Ag[r * 32 + c16];
    }

    // ---- preload B slice (chunk 0, slice 0) into buf 0 ----
    {
        const int n = t >> 3, ku = t & 7;
        uint4 v0 = bank0[n * 32 + ku];
        uint4 v1 = bank0[(n + 32) * 32 + ku];
        char* d = (char*)sB;                               // buf0, half0
        *(uint4*)(d + n * 144 + ku * 16) = v0;
        *(uint4*)(d + (n + 32) * 144 + ku * 16) = v1;
        if (diff) {
            uint4 w0 = bank1[n * 32 + ku];
            uint4 w1 = bank1[(n + 32) * 32 + ku];
            char* d1 = (char*)(sB + SB_HALF_ELEM);
            *(uint4*)(d1 + n * 144 + ku * 16) = w0;
            *(uint4*)(d1 + (n + 32) * 144 + ku * 16) = w1;
        }
    }
    __syncthreads();

    int buf = 0;
    float m_run0 = NEG_HUGE, m_run1 = NEG_HUGE;
    float s_run0 = 0.f, s_run1 = 0.f;
    const int rbase = 16 * w;

    for (int chunk = 0; chunk < 32; ++chunk) {
        float acc[8][4];
#pragma unroll
        for (int i = 0; i < 8; ++i)
#pragma unroll
            for (int jj = 0; jj < 4; ++jj) acc[i][jj] = 0.f;

#pragma unroll
        for (int s = 0; s < 4; ++s) {
            const int step = chunk * 4 + s + 1;
            const bool has_next = (step < 128);
            uint4 p0a = {}, p0b = {}, p1a = {}, p1b = {};
            if (has_next) {
                const int c2 = step >> 2, s2 = step & 3;
                const int n0n = c2 * 64;
                const int n = t >> 3, ku = t & 7;
                p0a = bank0[(n0n + n) * 32 + s2 * 8 + ku];
                p0b = bank0[(n0n + n + 32) * 32 + s2 * 8 + ku];
                if (diff) {
                    p1a = bank1[(n0n + n) * 32 + s2 * 8 + ku];
                    p1b = bank1[(n0n + n + 32) * 32 + s2 * 8 + ku];
                }
            }

            // ---- MMA on current buffer ----
            const __nv_bfloat16* sBh = sB + (buf * 2 + myhalf) * SB_HALF_ELEM;
#pragma unroll
            for (int kk = 0; kk < 4; ++kk) {
                const int ka = s * 64 + kk * 16;
                unsigned a0, a1, a2, a3;
                unsigned aaddr = smem_u32((const char*)sA +
                                          (rbase + (lane & 15)) * 528 +
                                          (ka + 8 * (lane >> 4)) * 2);
                ldsm4(a0, a1, a2, a3, aaddr);
                const int kl = kk * 16;
#pragma unroll
                for (int tn = 0; tn < 4; ++tn) {
                    unsigned b0, b1, b2, b3;
                    const int nrow = tn * 16 + (lane & 7) + 8 * (lane >> 4);
                    const int kcol = kl + 8 * ((lane >> 3) & 1);
                    unsigned baddr = smem_u32((const char*)sBh + nrow * 144 + kcol * 2);
                    ldsm4(b0, b1, b2, b3, baddr);
                    mma_bf16(acc[2 * tn], a0, a1, a2, a3, b0, b1);
                    mma_bf16(acc[2 * tn + 1], a0, a1, a2, a3, b2, b3);
                }
            }

            if (has_next) {
                const int n = t >> 3, ku = t & 7;
                char* d = (char*)(sB + ((buf ^ 1) * 2) * SB_HALF_ELEM);
                *(uint4*)(d + n * 144 + ku * 16) = p0a;
                *(uint4*)(d + (n + 32) * 144 + ku * 16) = p0b;
                if (diff) {
                    char* d1 = (char*)(sB + ((buf ^ 1) * 2 + 1) * SB_HALF_ELEM);
                    *(uint4*)(d1 + n * 144 + ku * 16) = p1a;
                    *(uint4*)(d1 + (n + 32) * 144 + ku * 16) = p1b;
                }
            }
            __syncthreads();
            buf ^= 1;
        }

        // ---- online softmax update for this 64-col chunk ----
        float mx0 = NEG_HUGE, mx1 = NEG_HUGE;
#pragma unroll
        for (int tl = 0; tl < 8; ++tl) {
            acc[tl][0] *= INV_TEMP; acc[tl][1] *= INV_TEMP;
            acc[tl][2] *= INV_TEMP; acc[tl][3] *= INV_TEMP;
            mx0 = fmaxf(mx0, fmaxf(acc[tl][0], acc[tl][1]));
            mx1 = fmaxf(mx1, fmaxf(acc[tl][2], acc[tl][3]));
        }
        mx0 = fmaxf(mx0, __shfl_xor_sync(~0u, mx0, 1));
        mx0 = fmaxf(mx0, __shfl_xor_sync(~0u, mx0, 2));
        mx1 = fmaxf(mx1, __shfl_xor_sync(~0u, mx1, 1));
        mx1 = fmaxf(mx1, __shfl_xor_sync(~0u, mx1, 2));
        const float nm0 = fmaxf(m_run0, mx0);
        const float nm1 = fmaxf(m_run1, mx1);
        float sum0 = 0.f, sum1 = 0.f;
#pragma unroll
        for (int tl = 0; tl < 8; ++tl) {
            sum0 += __expf(acc[tl][0] - nm0) + __expf(acc[tl][1] - nm0);
            sum1 += __expf(acc[tl][2] - nm1) + __expf(acc[tl][3] - nm1);
        }
        sum0 += __shfl_xor_sync(~0u, sum0, 1);
        sum0 += __shfl_xor_sync(~0u, sum0, 2);
        sum1 += __shfl_xor_sync(~0u, sum1, 1);
        sum1 += __shfl_xor_sync(~0u, sum1, 2);
        s_run0 = s_run0 * __expf(m_run0 - nm0) + sum0;
        s_run1 = s_run1 * __expf(m_run1 - nm1) + sum1;
        m_run0 = nm0;
        m_run1 = nm1;
    }

    // ---- finalize per-row loss (lanes with lane%4==0 own unique rows) ----
    float lsum = 0.f;
    if ((lane & 3) == 0) {
        const int r0 = q * 128 + rbase + (lane >> 2);
        const float p0 = g_pos_sim[r0];
        const float p1 = g_pos_sim[r0 + 8];
        float mf = fmaxf(m_run0, p0);
        float ep = __expf(p0 - mf);
        float denom = s_run0 * __expf(m_run0 - mf) + ep + EPSV;
        lsum = -logf(ep / denom + EPSV);
        mf = fmaxf(m_run1, p1);
        ep = __expf(p1 - mf);
        denom = s_run1 * __expf(m_run1 - mf) + ep + EPSV;
        lsum += -logf(ep / denom + EPSV);
    }
#pragma unroll
    for (int o = 16; o; o >>= 1) lsum += __shfl_xor_sync(~0u, lsum, o);
    if (lane == 0) red[w] = lsum;
    __syncthreads();
    if (t == 0) {
        float tot = 0.f;
#pragma unroll
        for (int i = 0; i < 8; ++i) tot += red[i];
        g_part[q] = tot;
    }
}

// ---------------------------------------------------------------------------
// 5) deterministic final reduction -> mean loss
// ---------------------------------------------------------------------------
__global__ void finalize_kernel(float* __restrict__ out) {
    __shared__ float sred[8];
    const int t = threadIdx.x;
    float v = g_part[t];
#pragma unroll
    for (int o = 16; o; o >>= 1) v += __shfl_xor_sync(~0u, v, o);
    if ((t & 31) == 0) sred[t >> 5] = v;
    __syncthreads();
    if (t == 0) {
        float tot = 0.f;
#pragma unroll
        for (int i = 0; i < 8; ++i) tot += sred[i];
        out[0] = tot * (1.f / 32768.f);
    }
}

// ---------------------------------------------------------------------------
extern "C" void kernel_launch(void* const* d_in, const int* in_sizes, int n_in,
                              void* d_out, int out_size) {
    const float* mainp = (const float*)d_in[0];
    const float* emap  = (const float*)d_in[1];
    const float* lab   = (const float*)d_in[2];
    const float* neg   = (const float*)d_in[3];
    const float* pos   = (const float*)d_in[4];
    float* out = (float*)d_out;

    cudaFuncSetAttribute(gemm_softmax_kernel,
                         cudaFuncAttributeMaxDynamicSharedMemorySize, SMEM_MAIN);

    label_kernel<<<NPATCH, 256>>>(lab);
    convert_bank_kernel<<<64, 256>>>(neg, pos);
    convert_anchor_kernel<<<NPATCH, 256>>>(mainp, emap);
    gemm_softmax_kernel<<<256, 256, SMEM_MAIN>>>();
    finalize_kernel<<<1, 256>>>(out);
}

// round 4
// speedup vs baseline: 1.0104x; 1.0104x over previous
#include <cuda_runtime.h>
#include <cuda_bf16.h>
#include <cstdint>

// ---------------------------------------------------------------------------
// ContrastivePatchLoss — mma.sync (HMMA) fused GEMM+softmax, full-K tiles.
// 512 patches x 64 rows x C=256 vs bank 2048x256. exp2-domain softmax.
// ---------------------------------------------------------------------------

#define NPATCH   512
#define ROWS_TOT 32768
#define NBANK    2048
#define EPSV     1e-5f
#define SCALEF   2.8853900817779268f   // (1/0.5) * log2(e)
#define NEG_HUGE (-1e30f)
#define PITCH    528                   // bytes per row in smem tiles
#define TILEB    (128 * PITCH)         // 67584

__device__ __nv_bfloat16 g_A[ROWS_TOT * 256];     // scaled anchors (permuted slots)
__device__ __nv_bfloat16 g_negB[NBANK * 256];
__device__ __nv_bfloat16 g_posB[NBANK * 256];
__device__ float g_pos_sim[ROWS_TOT];             // scaled pos logits (permuted)
__device__ int   g_flags[NPATCH];
__device__ int   g_slot[NPATCH];
__device__ int   g_pairinfo[256];
__device__ float g_part[256];

// ---------------------------------------------------------------------------
__device__ __forceinline__ unsigned sm2u(const void* p) {
    return (unsigned)__cvta_generic_to_shared(p);
}
__device__ __forceinline__ float ex2f(float x) {
    float y; asm("ex2.approx.f32 %0, %1;" : "=f"(y) : "f"(x)); return y;
}
__device__ __forceinline__ void ldsm4(unsigned& r0, unsigned& r1, unsigned& r2, unsigned& r3,
                                      unsigned addr) {
    asm volatile("ldmatrix.sync.aligned.m8n8.x4.shared.b16 {%0,%1,%2,%3}, [%4];\n"
                 : "=r"(r0), "=r"(r1), "=r"(r2), "=r"(r3) : "r"(addr));
}
__device__ __forceinline__ void mma_bf16(float* c, unsigned a0, unsigned a1, unsigned a2,
                                         unsigned a3, unsigned b0, unsigned b1) {
    asm volatile("mma.sync.aligned.m16n8k16.row.col.f32.bf16.bf16.f32 "
                 "{%0,%1,%2,%3},{%4,%5,%6,%7},{%8,%9},{%0,%1,%2,%3};\n"
                 : "+f"(c[0]), "+f"(c[1]), "+f"(c[2]), "+f"(c[3])
                 : "r"(a0), "r"(a1), "r"(a2), "r"(a3), "r"(b0), "r"(b1));
}

// 128 rows x 512B -> smem tile with pitch 528 via cp.async (16 x 16B per thread)
__device__ __forceinline__ void load_tile(unsigned dst_base, const char* src, int t) {
#pragma unroll
    for (int i = 0; i < 16; ++i) {
        const int u = i * 256 + t;
        const int row = u >> 5, c16 = u & 31;
        const unsigned dst = dst_base + (unsigned)(row * PITCH + c16 * 16);
        const char* s = src + ((size_t)row * 512 + (size_t)c16 * 16);
        asm volatile("cp.async.cg.shared.global [%0], [%1], 16;" :: "r"(dst), "l"(s) : "memory");
    }
    asm volatile("cp.async.commit_group;" ::: "memory");
}

// ---------------------------------------------------------------------------
// 1) label patch means -> flags
// ---------------------------------------------------------------------------
__global__ void label_kernel(const float* __restrict__ lab) {
    __shared__ float sred[8];
    const int p = blockIdx.x, t = threadIdx.x;
    const int b = p >> 6, j = (p >> 3) & 7, k = p & 7;
    const float* base = lab + (size_t)b * 65536 + (size_t)j * 32 * 256 + k * 32;
    float sum = 0.f;
#pragma unroll
    for (int it = 0; it < 4; ++it) {
        int u = t + 256 * it;
        int y = u >> 5, x = u & 31;
        sum += base[y * 256 + x];
    }
#pragma unroll
    for (int o = 16; o; o >>= 1) sum += __shfl_xor_sync(~0u, sum, o);
    if ((t & 31) == 0) sred[t >> 5] = sum;
    __syncthreads();
    if (t == 0) {
        float s2 = 0.f;
#pragma unroll
        for (int i = 0; i < 8; ++i) s2 += sred[i];
        g_flags[p] = (s2 * (1.f / 1024.f) < 0.1f) ? 1 : 0;
    }
}

// ---------------------------------------------------------------------------
// 2) permutation: sort patches by flag -> slots; pair info per CTA
// ---------------------------------------------------------------------------
__global__ void perm_kernel() {
    __shared__ int sc[512], sflag[512];
    const int t = threadIdx.x;
    const int f = g_flags[t];
    sc[t] = f;
    __syncthreads();
    for (int off = 1; off < 512; off <<= 1) {
        int add = (t >= off) ? sc[t - off] : 0;
        __syncthreads();
        sc[t] += add;
        __syncthreads();
    }
    const int npos = sc[511];
    const int slot = f ? (sc[t] - 1) : (npos + t - sc[t]);
    g_slot[t] = slot;
    sflag[slot] = f;
    __syncthreads();
    if (t < 256) g_pairinfo[t] = sflag[2 * t] | (sflag[2 * t + 1] << 1);
}

// ---------------------------------------------------------------------------
// 3) banks [32,256,8,8] f32 -> [2048,256] bf16
// ---------------------------------------------------------------------------
__global__ void convert_bank_kernel(const float* __restrict__ neg, const float* __restrict__ pos) {
    __shared__ __nv_bfloat16 sT[256][66];
    const int blk = blockIdx.x, t = threadIdx.x;
    const int bank = blk >> 5, l = blk & 31;
    const float* src = (bank ? pos : neg) + (size_t)l * 16384;
#pragma unroll 4
    for (int it = 0; it < 64; ++it) {
        int u = t + 256 * it;
        int c = u >> 6, s = u & 63;
        sT[c][s] = __float2bfloat16(src[c * 64 + s]);
    }
    __syncthreads();
    __nv_bfloat16* dst = (bank ? g_posB : g_negB) + (size_t)l * 64 * 256;
    unsigned* dst32 = (unsigned*)dst;
#pragma unroll 4
    for (int it = 0; it < 32; ++it) {
        int u = t + 256 * it;
        int s = u >> 7, cc = u & 127;
        unsigned lo = __bfloat16_as_ushort(sT[2 * cc][s]);
        unsigned hi = __bfloat16_as_ushort(sT[2 * cc + 1][s]);
        dst32[s * 128 + cc] = (hi << 16) | lo;
    }
}

// ---------------------------------------------------------------------------
// 4) anchors -> permuted scaled bf16 + scaled pos logits
// ---------------------------------------------------------------------------
__global__ void convert_anchor_kernel(const float* __restrict__ mainp,
                                      const float* __restrict__ emap) {
    __shared__ __nv_bfloat16 sA[64][258];
    __shared__ float sdot[4][64];
    const int p = blockIdx.x, t = threadIdx.x;
    const int slot = g_slot[p];
    const int b = p >> 6, j = (p >> 3) & 7, k = p & 7;
    const int n = t & 63, y = n >> 3, x = n & 7;
    const size_t base = (size_t)b * 1048576 + (size_t)(j * 8 + y) * 64 + (k * 8 + x);
    float dot = 0.f;
#pragma unroll 8
    for (int it = 0; it < 64; ++it) {
        int c = (t >> 6) + 4 * it;
        size_t g = base + (size_t)c * 4096;
        float mv = mainp[g];
        float ev = emap[g];
        dot += mv * ev;
        sA[n][c] = __float2bfloat16(mv * SCALEF);
    }
    sdot[t >> 6][n] = dot;
    __syncthreads();
    if (t < 64) {
        float d = sdot[0][t] + sdot[1][t] + sdot[2][t] + sdot[3][t];
        g_pos_sim[slot * 64 + t] = d * SCALEF;
    }
    unsigned* A32 = (unsigned*)g_A;
#pragma unroll 4
    for (int it = 0; it < 32; ++it) {
        int u = t + 256 * it;
        int n2 = u >> 7, cc = u & 127;
        unsigned v = *(const unsigned*)((const char*)&sA[0][0] + (size_t)n2 * 516 + cc * 4);
        A32[((size_t)slot * 64 + n2) * 128 + cc] = v;
    }
}

// ---------------------------------------------------------------------------
// 5) HMMA GEMM + online softmax. grid 256, block 256 (8 warps).
//    smem: A tile + 2x B tile, pitch 528 -> 202752 B dynamic.
//    Chunks: 16 (non-mixed) of 128 bank rows, full K=256 per chunk.
// ---------------------------------------------------------------------------
#define SMEM_DYN (3 * TILEB)

__global__ __launch_bounds__(256, 1) void gemm_hmma_kernel() {
    extern __shared__ __align__(16) unsigned char dsm[];
    __shared__ float red[8];

    const int t = threadIdx.x, w = t >> 5, lane = t & 31, q = blockIdx.x;
    const unsigned sA_u = sm2u(dsm);
    const unsigned sB_u[2] = { sA_u + TILEB, sA_u + 2 * TILEB };

    const int info = g_pairinfo[q];
    const int f0 = info & 1, f1 = (info >> 1) & 1;
    const int mixed = (f0 != f1);
    const int nch = mixed ? 32 : 16;

    const char* negc = (const char*)g_negB;
    const char* posc = (const char*)g_posB;
    auto bsrc = [&](int cc) -> const char* {
        const int f = mixed ? ((cc >> 4) ? f1 : f0) : f0;
        return (f ? posc : negc) + (size_t)(cc & 15) * 65536;
    };

    // preload A + B(chunk0)
    load_tile(sA_u, (const char*)g_A + (size_t)q * 65536, t);
    load_tile(sB_u[0], bsrc(0), t);
    asm volatile("cp.async.wait_group 0;" ::: "memory");
    __syncthreads();

    float m1 = NEG_HUGE, s1 = 0.f, m2 = NEG_HUGE, s2 = 0.f;
    const int rbase = 16 * w;
    const unsigned a_base = sA_u + (unsigned)((rbase + (lane & 15)) * PITCH + (lane >> 4) * 16);
    const unsigned b_off = (unsigned)(((lane & 7) + 8 * (lane >> 4)) * PITCH +
                                      ((lane >> 3) & 1) * 16);

    for (int cc = 0; cc < nch; ++cc) {
        const int buf = cc & 1;
        if (cc + 1 < nch) load_tile(sB_u[buf ^ 1], bsrc(cc + 1), t);

        const bool active = !mixed || ((w >> 2) == (cc >> 4));
        if (active) {
            float acc[16][4];
#pragma unroll
            for (int i = 0; i < 16; ++i) {
                acc[i][0] = 0.f; acc[i][1] = 0.f; acc[i][2] = 0.f; acc[i][3] = 0.f;
            }
            const unsigned b_base = sB_u[buf] + b_off;
#pragma unroll
            for (int ks = 0; ks < 16; ++ks) {
                unsigned a0, a1, a2, a3;
                ldsm4(a0, a1, a2, a3, a_base + (unsigned)(ks * 32));
#pragma unroll
                for (int nt = 0; nt < 8; ++nt) {
                    unsigned b0, b1, b2, b3;
                    ldsm4(b0, b1, b2, b3, b_base + (unsigned)(nt * 16 * PITCH + ks * 32));
                    mma_bf16(acc[2 * nt], a0, a1, a2, a3, b0, b1);
                    mma_bf16(acc[2 * nt + 1], a0, a1, a2, a3, b2, b3);
                }
            }
            // ---- online softmax update (rows r1 = rbase+(lane>>2), r2 = r1+8) ----
            float mxA = NEG_HUGE, mxB = NEG_HUGE, mxC = NEG_HUGE, mxD = NEG_HUGE;
#pragma unroll
            for (int i = 0; i < 16; ++i) {
                mxA = fmaxf(mxA, acc[i][0]); mxB = fmaxf(mxB, acc[i][1]);
                mxC = fmaxf(mxC, acc[i][2]); mxD = fmaxf(mxD, acc[i][3]);
            }
            float mx1 = fmaxf(mxA, mxB), mx2 = fmaxf(mxC, mxD);
            mx1 = fmaxf(mx1, __shfl_xor_sync(~0u, mx1, 1));
            mx1 = fmaxf(mx1, __shfl_xor_sync(~0u, mx1, 2));
            mx2 = fmaxf(mx2, __shfl_xor_sync(~0u, mx2, 1));
            mx2 = fmaxf(mx2, __shfl_xor_sync(~0u, mx2, 2));
            const float nm1 = fmaxf(m1, mx1), nm2 = fmaxf(m2, mx2);
            float aA = 0.f, aB = 0.f, aC = 0.f, aD = 0.f;
#pragma unroll
            for (int i = 0; i < 16; ++i) {
                aA += ex2f(acc[i][0] - nm1); aB += ex2f(acc[i][1] - nm1);
                aC += ex2f(acc[i][2] - nm2); aD += ex2f(acc[i][3] - nm2);
            }
            float su1 = aA + aB, su2 = aC + aD;
            su1 += __shfl_xor_sync(~0u, su1, 1);
            su1 += __shfl_xor_sync(~0u, su1, 2);
            su2 += __shfl_xor_sync(~0u, su2, 1);
            su2 += __shfl_xor_sync(~0u, su2, 2);
            s1 = s1 * ex2f(m1 - nm1) + su1; m1 = nm1;
            s2 = s2 * ex2f(m2 - nm2) + su2; m2 = nm2;
        }
        if (cc + 1 < nch) asm volatile("cp.async.wait_group 0;" ::: "memory");
        __syncthreads();
    }

    // ---- per-row loss (lane%4==0 owns rows r1, r2) ----
    float loss = 0.f;
    if ((lane & 3) == 0) {
        const int r = q * 128 + rbase + (lane >> 2);
        const float p1 = g_pos_sim[r];
        const float p2 = g_pos_sim[r + 8];
        float mf = fmaxf(m1, p1);
        float ep = ex2f(p1 - mf);
        float denom = s1 * ex2f(m1 - mf) + ep + EPSV;
        loss = -logf(ep / denom + EPSV);
        mf = fmaxf(m2, p2);
        ep = ex2f(p2 - mf);
        denom = s2 * ex2f(m2 - mf) + ep + EPSV;
        loss += -logf(ep / denom + EPSV);
    }
#pragma unroll
    for (int o = 16; o; o >>= 1) loss += __shfl_xor_sync(~0u, loss, o);
    if (lane == 0) red[w] = loss;
    __syncthreads();
    if (t == 0) {
        float tot = 0.f;
#pragma unroll
        for (int i = 0; i < 8; ++i) tot += red[i];
        g_part[q] = tot;
    }
}

// ---------------------------------------------------------------------------
// 6) final reduction
// ---------------------------------------------------------------------------
__global__ void finalize_kernel(float* __restrict__ out) {
    __shared__ float sred[8];
    const int t = threadIdx.x;
    float v = g_part[t];
#pragma unroll
    for (int o = 16; o; o >>= 1) v += __shfl_xor_sync(~0u, v, o);
    if ((t & 31) == 0) sred[t >> 5] = v;
    __syncthreads();
    if (t == 0) {
        float tot = 0.f;
#pragma unroll
        for (int i = 0; i < 8; ++i) tot += sred[i];
        out[0] = tot * (1.f / 32768.f);
    }
}

// ---------------------------------------------------------------------------
extern "C" void kernel_launch(void* const* d_in, const int* in_sizes, int n_in,
                              void* d_out, int out_size) {
    const float* mainp = (const float*)d_in[0];
    const float* emap  = (const float*)d_in[1];
    const float* lab   = (const float*)d_in[2];
    const float* neg   = (const float*)d_in[3];
    const float* pos   = (const float*)d_in[4];
    float* out = (float*)d_out;

    cudaFuncSetAttribute(gemm_hmma_kernel,
                         cudaFuncAttributeMaxDynamicSharedMemorySize, SMEM_DYN);

    label_kernel<<<NPATCH, 256>>>(lab);
    perm_kernel<<<1, 512>>>();
    convert_bank_kernel<<<64, 256>>>(neg, pos);
    convert_anchor_kernel<<<NPATCH, 256>>>(mainp, emap);
    gemm_hmma_kernel<<<256, 256, SMEM_DYN>>>();
    finalize_kernel<<<1, 256>>>(out);
}

// round 5
// speedup vs baseline: 1.1918x; 1.1795x over previous
#include <cuda_runtime.h>
#include <cuda_bf16.h>
#include <cstdint>

// ---------------------------------------------------------------------------
// ContrastivePatchLoss — HMMA fused GEMM+softmax, 4Mx2N warp tiling,
// blocked A layout [slot][yin][c][xin] with ldmatrix.trans A-fragments.
// ---------------------------------------------------------------------------

#define NPATCH   512
#define ROWS_TOT 32768
#define NBANK    2048
#define EPSV     1e-5f
#define SCALEF   2.8853900817779268f   // (1/0.5) * log2(e)
#define NEG_HUGE (-1e30f)
#define PITCH    528                   // bytes per row in B smem tiles
#define TILEB    (128 * PITCH)         // 67584

// g_A blocked: [slot(512)][yin(8)][c(256)][xin(8)] bf16  (16B per (slot,yin,c))
__device__ __nv_bfloat16 g_A[ROWS_TOT * 256];
__device__ __nv_bfloat16 g_negB[NBANK * 256];     // [row][c] bf16
__device__ __nv_bfloat16 g_posB[NBANK * 256];
__device__ float g_pos_sim[ROWS_TOT];             // log2-domain pos logits (permuted rows)
__device__ int   g_flags[NPATCH];
__device__ int   g_slot[NPATCH];
__device__ int   g_pairinfo[256];
__device__ float g_part[256];

// ---------------------------------------------------------------------------
__device__ __forceinline__ unsigned sm2u(const void* p) {
    return (unsigned)__cvta_generic_to_shared(p);
}
__device__ __forceinline__ float ex2f(float x) {
    float y; asm("ex2.approx.f32 %0, %1;" : "=f"(y) : "f"(x)); return y;
}
__device__ __forceinline__ void ldsm4(unsigned& r0, unsigned& r1, unsigned& r2, unsigned& r3,
                                      unsigned addr) {
    asm volatile("ldmatrix.sync.aligned.m8n8.x4.shared.b16 {%0,%1,%2,%3}, [%4];\n"
                 : "=r"(r0), "=r"(r1), "=r"(r2), "=r"(r3) : "r"(addr));
}
__device__ __forceinline__ void ldsm4t(unsigned& r0, unsigned& r1, unsigned& r2, unsigned& r3,
                                       unsigned addr) {
    asm volatile("ldmatrix.sync.aligned.m8n8.x4.trans.shared.b16 {%0,%1,%2,%3}, [%4];\n"
                 : "=r"(r0), "=r"(r1), "=r"(r2), "=r"(r3) : "r"(addr));
}
__device__ __forceinline__ void mma_bf16(float* c, unsigned a0, unsigned a1, unsigned a2,
                                         unsigned a3, unsigned b0, unsigned b1) {
    asm volatile("mma.sync.aligned.m16n8k16.row.col.f32.bf16.bf16.f32 "
                 "{%0,%1,%2,%3},{%4,%5,%6,%7},{%8,%9},{%0,%1,%2,%3};\n"
                 : "+f"(c[0]), "+f"(c[1]), "+f"(c[2]), "+f"(c[3])
                 : "r"(a0), "r"(a1), "r"(a2), "r"(a3), "r"(b0), "r"(b1));
}

// B tile: 128 rows x 512B -> smem pitch 528 via cp.async
__device__ __forceinline__ void load_tile_b(unsigned dst_base, const char* src, int t) {
#pragma unroll
    for (int i = 0; i < 16; ++i) {
        const int u = i * 256 + t;
        const int row = u >> 5, c16 = u & 31;
        const unsigned dst = dst_base + (unsigned)(row * PITCH + c16 * 16);
        const char* s = src + ((size_t)row * 512 + (size_t)c16 * 16);
        asm volatile("cp.async.cg.shared.global [%0], [%1], 16;" :: "r"(dst), "l"(s) : "memory");
    }
    asm volatile("cp.async.commit_group;" ::: "memory");
}

// ---------------------------------------------------------------------------
// 1) label patch means -> flags
// ---------------------------------------------------------------------------
__global__ void label_kernel(const float* __restrict__ lab) {
    __shared__ float sred[8];
    const int p = blockIdx.x, t = threadIdx.x;
    const int b = p >> 6, j = (p >> 3) & 7, k = p & 7;
    const float* base = lab + (size_t)b * 65536 + (size_t)j * 32 * 256 + k * 32;
    float sum = 0.f;
#pragma unroll
    for (int it = 0; it < 4; ++it) {
        int u = t + 256 * it;
        int y = u >> 5, x = u & 31;
        sum += base[y * 256 + x];
    }
#pragma unroll
    for (int o = 16; o; o >>= 1) sum += __shfl_xor_sync(~0u, sum, o);
    if ((t & 31) == 0) sred[t >> 5] = sum;
    __syncthreads();
    if (t == 0) {
        float s2 = 0.f;
#pragma unroll
        for (int i = 0; i < 8; ++i) s2 += sred[i];
        g_flags[p] = (s2 * (1.f / 1024.f) < 0.1f) ? 1 : 0;
    }
}

// ---------------------------------------------------------------------------
// 2) permutation: sort patches by flag -> slots; pair info per CTA
// ---------------------------------------------------------------------------
__global__ void perm_kernel() {
    __shared__ int sc[512], sflag[512];
    const int t = threadIdx.x;
    const int f = g_flags[t];
    sc[t] = f;
    __syncthreads();
    for (int off = 1; off < 512; off <<= 1) {
        int add = (t >= off) ? sc[t - off] : 0;
        __syncthreads();
        sc[t] += add;
        __syncthreads();
    }
    const int npos = sc[511];
    const int slot = f ? (sc[t] - 1) : (npos + t - sc[t]);
    g_slot[t] = slot;
    sflag[slot] = f;
    __syncthreads();
    if (t < 256) g_pairinfo[t] = sflag[2 * t] | (sflag[2 * t + 1] << 1);
}

// ---------------------------------------------------------------------------
// 3) banks [32,256,8,8] f32 -> [2048,256] bf16
// ---------------------------------------------------------------------------
__global__ void convert_bank_kernel(const float* __restrict__ neg, const float* __restrict__ pos) {
    __shared__ __nv_bfloat16 sT[256][66];
    const int blk = blockIdx.x, t = threadIdx.x;
    const int bank = blk >> 5, l = blk & 31;
    const float* src = (bank ? pos : neg) + (size_t)l * 16384;
#pragma unroll 4
    for (int it = 0; it < 64; ++it) {
        int u = t + 256 * it;
        int c = u >> 6, s = u & 63;
        sT[c][s] = __float2bfloat16(src[c * 64 + s]);
    }
    __syncthreads();
    __nv_bfloat16* dst = (bank ? g_posB : g_negB) + (size_t)l * 64 * 256;
    unsigned* dst32 = (unsigned*)dst;
#pragma unroll 4
    for (int it = 0; it < 32; ++it) {
        int u = t + 256 * it;
        int s = u >> 7, cc = u & 127;
        unsigned lo = __bfloat16_as_ushort(sT[2 * cc][s]);
        unsigned hi = __bfloat16_as_ushort(sT[2 * cc + 1][s]);
        dst32[s * 128 + cc] = (hi << 16) | lo;
    }
}

// ---------------------------------------------------------------------------
// 4) anchors: block = (b, y_global). Coalesced float4 reads of one W-row per
//    channel; 8B blocked writes into g_A[slot][yin][c][xin]; exact fp32 pos dot.
// ---------------------------------------------------------------------------
__global__ void convert_anchor_kernel(const float* __restrict__ mainp,
                                      const float* __restrict__ emap) {
    __shared__ float sdot[16][65];
    __shared__ int sslot[8];
    const int bid = blockIdx.x, t = threadIdx.x;
    const int b = bid >> 6, y = bid & 63;
    const int j = y >> 3, yin = y & 7;
    if (t < 8) sslot[t] = g_slot[b * 64 + j * 8 + t];
    __syncthreads();

    const int g = t & 15, r = t >> 4;
    const int slot = sslot[g >> 1];
    const unsigned xh = (unsigned)(g & 1);
    const size_t base4 = ((size_t)b * 256 * 64 + y) * 16 + g;   // float4 units, c=0
    const float4* mp = (const float4*)mainp;
    const float4* ep = (const float4*)emap;
    uint2* Aout = (uint2*)g_A;

    float d0 = 0.f, d1 = 0.f, d2 = 0.f, d3 = 0.f;
#pragma unroll
    for (int it = 0; it < 16; ++it) {
        const int c = r + 16 * it;
        const size_t o = base4 + (size_t)c * 1024;
        const float4 mv = mp[o];
        const float4 ev = ep[o];
        d0 += mv.x * ev.x; d1 += mv.y * ev.y; d2 += mv.z * ev.z; d3 += mv.w * ev.w;
        const __nv_bfloat162 lo = __floats2bfloat162_rn(mv.x * SCALEF, mv.y * SCALEF);
        const __nv_bfloat162 hi = __floats2bfloat162_rn(mv.z * SCALEF, mv.w * SCALEF);
        uint2 v;
        v.x = *(const unsigned*)&lo;
        v.y = *(const unsigned*)&hi;
        Aout[(size_t)((slot * 8 + yin) * 256 + c) * 2 + xh] = v;
    }
    sdot[r][4 * g + 0] = d0; sdot[r][4 * g + 1] = d1;
    sdot[r][4 * g + 2] = d2; sdot[r][4 * g + 3] = d3;
    __syncthreads();
    if (t < 64) {
        float dd = 0.f;
#pragma unroll
        for (int i = 0; i < 16; ++i) dd += sdot[i][t];
        g_pos_sim[sslot[t >> 3] * 64 + yin * 8 + (t & 7)] = dd * SCALEF;
    }
}

// ---------------------------------------------------------------------------
// 5) HMMA GEMM + online softmax. grid 256, block 256 (8 warps, 4M x 2N).
//    A smem: 64KB linear blocked layout; B: 2 x pitched tile.
// ---------------------------------------------------------------------------
#define SMEM_DYN (65536 + 2 * TILEB)

__global__ __launch_bounds__(256, 1) void gemm_hmma_kernel() {
    extern __shared__ __align__(16) unsigned char dsm[];
    __shared__ float sh_m[128], sh_s[128], red[8];

    const int t = threadIdx.x, w = t >> 5, lane = t & 31, q = blockIdx.x;
    const unsigned sA_u = sm2u(dsm);
    const unsigned sB_u[2] = { sA_u + 65536u, sA_u + 65536u + TILEB };

    const int info = g_pairinfo[q];
    const int f0 = info & 1, f1 = (info >> 1) & 1;
    const int mixed = (f0 != f1);
    const int nch = mixed ? 32 : 16;

    const char* negc = (const char*)g_negB;
    const char* posc = (const char*)g_posB;
    auto bsrc = [&](int cc) -> const char* {
        const int f = mixed ? ((cc >> 4) ? f1 : f0) : f0;
        return (f ? posc : negc) + (size_t)(cc & 15) * 65536;
    };

    // preload A (linear 64KB) + B(chunk0)
    {
        const char* Ag = (const char*)g_A + (size_t)q * 65536;
#pragma unroll
        for (int i = 0; i < 16; ++i) {
            const int u = i * 256 + t;
            asm volatile("cp.async.cg.shared.global [%0], [%1], 16;"
                         :: "r"(sA_u + (unsigned)(u * 16)), "l"(Ag + (size_t)u * 16) : "memory");
        }
        asm volatile("cp.async.commit_group;" ::: "memory");
    }
    load_tile_b(sB_u[0], bsrc(0), t);
    asm volatile("cp.async.wait_group 0;" ::: "memory");
    __syncthreads();

    const int mw = w & 3, nw = w >> 2;
    // A ldsm.trans lane address (within group block): grp-sel + c-offset + 16B row
    const unsigned a_lane = (unsigned)(((lane >> 3) & 1) * 4096 +
                                       ((lane & 7) + 8 * (lane >> 4)) * 16);
    const unsigned a_base = sA_u + (unsigned)(mw * 16384) + a_lane;
    const unsigned b_off = (unsigned)((nw * 64 + (lane & 7) + 8 * (lane >> 4)) * PITCH +
                                      ((lane >> 3) & 1) * 16);

    float m_st[4] = {NEG_HUGE, NEG_HUGE, NEG_HUGE, NEG_HUGE};
    float s_st[4] = {0.f, 0.f, 0.f, 0.f};

    for (int cc = 0; cc < nch; ++cc) {
        const int buf = cc & 1;
        if (cc + 1 < nch) load_tile_b(sB_u[buf ^ 1], bsrc(cc + 1), t);

        const bool active = !mixed || ((mw >> 1) == (cc >> 4));
        if (active) {
            float acc[2][4][2][4];
#pragma unroll
            for (int f = 0; f < 2; ++f)
#pragma unroll
                for (int nt = 0; nt < 4; ++nt)
#pragma unroll
                    for (int p = 0; p < 2; ++p) {
                        acc[f][nt][p][0] = 0.f; acc[f][nt][p][1] = 0.f;
                        acc[f][nt][p][2] = 0.f; acc[f][nt][p][3] = 0.f;
                    }
            const unsigned bb = sB_u[buf] + b_off;
#pragma unroll
            for (int ks = 0; ks < 16; ++ks) {
                unsigned a[2][4];
                ldsm4t(a[0][0], a[0][1], a[0][2], a[0][3], a_base + (unsigned)(ks * 256));
                ldsm4t(a[1][0], a[1][1], a[1][2], a[1][3],
                       a_base + (unsigned)(8192 + ks * 256));
#pragma unroll
                for (int nt = 0; nt < 4; ++nt) {
                    unsigned b0, b1, b2, b3;
                    ldsm4(b0, b1, b2, b3, bb + (unsigned)(nt * 16 * PITCH + ks * 32));
                    mma_bf16(acc[0][nt][0], a[0][0], a[0][1], a[0][2], a[0][3], b0, b1);
                    mma_bf16(acc[0][nt][1], a[0][0], a[0][1], a[0][2], a[0][3], b2, b3);
                    mma_bf16(acc[1][nt][0], a[1][0], a[1][1], a[1][2], a[1][3], b0, b1);
                    mma_bf16(acc[1][nt][1], a[1][0], a[1][1], a[1][2], a[1][3], b2, b3);
                }
            }
            // ---- online softmax (4 row-slots: idx = f*2 + h) ----
#pragma unroll
            for (int idx = 0; idx < 4; ++idx) {
                const int f = idx >> 1, h2 = (idx & 1) * 2;
                float mx = NEG_HUGE;
#pragma unroll
                for (int nt = 0; nt < 4; ++nt)
#pragma unroll
                    for (int p = 0; p < 2; ++p)
                        mx = fmaxf(mx, fmaxf(acc[f][nt][p][h2], acc[f][nt][p][h2 + 1]));
                mx = fmaxf(mx, __shfl_xor_sync(~0u, mx, 1));
                mx = fmaxf(mx, __shfl_xor_sync(~0u, mx, 2));
                const float nm = fmaxf(m_st[idx], mx);
                float aa = 0.f, ab = 0.f;
#pragma unroll
                for (int nt = 0; nt < 4; ++nt)
#pragma unroll
                    for (int p = 0; p < 2; ++p) {
                        aa += ex2f(acc[f][nt][p][h2] - nm);
                        ab += ex2f(acc[f][nt][p][h2 + 1] - nm);
                    }
                float su = aa + ab;
                su += __shfl_xor_sync(~0u, su, 1);
                su += __shfl_xor_sync(~0u, su, 2);
                s_st[idx] = s_st[idx] * ex2f(m_st[idx] - nm) + su;
                m_st[idx] = nm;
            }
        }
        if (cc + 1 < nch) asm volatile("cp.async.wait_group 0;" ::: "memory");
        __syncthreads();
    }

    // ---- combine the two N-half warps per row, then per-row loss ----
    if (nw == 1 && (lane & 3) == 0) {
#pragma unroll
        for (int idx = 0; idx < 4; ++idx) {
            const int row = mw * 32 + (idx >> 1) * 16 + (lane >> 2) + 8 * (idx & 1);
            sh_m[row] = m_st[idx];
            sh_s[row] = s_st[idx];
        }
    }
    __syncthreads();
    float loss = 0.f;
    if (nw == 0 && (lane & 3) == 0) {
#pragma unroll
        for (int idx = 0; idx < 4; ++idx) {
            const int row = mw * 32 + (idx >> 1) * 16 + (lane >> 2) + 8 * (idx & 1);
            const float m2 = sh_m[row], s2 = sh_s[row];
            const float M = fmaxf(m_st[idx], m2);
            const float S = s_st[idx] * ex2f(m_st[idx] - M) + s2 * ex2f(m2 - M);
            const float p = g_pos_sim[q * 128 + row];
            const float mf = fmaxf(M, p);
            const float ep = ex2f(p - mf);
            const float denom = S * ex2f(M - mf) + ep + EPSV;
            loss += -logf(ep / denom + EPSV);
        }
    }
#pragma unroll
    for (int o = 16; o; o >>= 1) loss += __shfl_xor_sync(~0u, loss, o);
    if (lane == 0) red[w] = loss;
    __syncthreads();
    if (t == 0) {
        float tot = 0.f;
#pragma unroll
        for (int i = 0; i < 8; ++i) tot += red[i];
        g_part[q] = tot;
    }
}

// ---------------------------------------------------------------------------
// 6) final reduction
// ---------------------------------------------------------------------------
__global__ void finalize_kernel(float* __restrict__ out) {
    __shared__ float sred[8];
    const int t = threadIdx.x;
    float v = g_part[t];
#pragma unroll
    for (int o = 16; o; o >>= 1) v += __shfl_xor_sync(~0u, v, o);
    if ((t & 31) == 0) sred[t >> 5] = v;
    __syncthreads();
    if (t == 0) {
        float tot = 0.f;
#pragma unroll
        for (int i = 0; i < 8; ++i) tot += sred[i];
        out[0] = tot * (1.f / 32768.f);
    }
}

// ---------------------------------------------------------------------------
extern "C" void kernel_launch(void* const* d_in, const int* in_sizes, int n_in,
                              void* d_out, int out_size) {
    const float* mainp = (const float*)d_in[0];
    const float* emap  = (const float*)d_in[1];
    const float* lab   = (const float*)d_in[2];
    const float* neg   = (const float*)d_in[3];
    const float* pos   = (const float*)d_in[4];
    float* out = (float*)d_out;

    cudaFuncSetAttribute(gemm_hmma_kernel,
                         cudaFuncAttributeMaxDynamicSharedMemorySize, SMEM_DYN);

    label_kernel<<<NPATCH, 256>>>(lab);
    perm_kernel<<<1, 512>>>();
    convert_bank_kernel<<<64, 256>>>(neg, pos);
    convert_anchor_kernel<<<NPATCH, 256>>>(mainp, emap);
    gemm_hmma_kernel<<<256, 256, SMEM_DYN>>>();
    finalize_kernel<<<1, 256>>>(out);
}

// round 6
// speedup vs baseline: 1.2312x; 1.0331x over previous
#include <cuda_runtime.h>
#include <cuda_fp16.h>
#include <cstdint>

// ---------------------------------------------------------------------------
// ContrastivePatchLoss — HMMA f16-accumulate fused GEMM+softmax.
// 4Mx2N warp tiling, blocked A layout, exp2-domain softmax in half2.
// ---------------------------------------------------------------------------

#define NPATCH   512
#define ROWS_TOT 32768
#define NBANK    2048
#define EPSV     1e-5f
#define SCALEF   2.8853900817779268f   // (1/0.5) * log2(e)
#define NEG_HUGE (-1e30f)
#define PITCH    528                   // bytes per row in B smem tiles
#define TILEB    (128 * PITCH)         // 67584

// g_A blocked: [slot(512)][yin(8)][c(256)][xin(8)] fp16 (16B per (slot,yin,c))
__device__ __half g_A[ROWS_TOT * 256];
__device__ __half g_negB[NBANK * 256];            // [row][c] fp16
__device__ __half g_posB[NBANK * 256];
__device__ float g_pos_sim[ROWS_TOT];             // log2-domain pos logits (permuted rows)
__device__ int   g_flags[NPATCH];
__device__ int   g_slot[NPATCH];
__device__ int   g_pairinfo[256];
__device__ float g_part[256];

// ---------------------------------------------------------------------------
__device__ __forceinline__ unsigned sm2u(const void* p) {
    return (unsigned)__cvta_generic_to_shared(p);
}
__device__ __forceinline__ float ex2f(float x) {
    float y; asm("ex2.approx.f32 %0, %1;" : "=f"(y) : "f"(x)); return y;
}
__device__ __forceinline__ __half2 h2ex2(__half2 x) {
    __half2 y;
    asm("ex2.approx.f16x2 %0, %1;"
        : "=r"(*(unsigned*)&y) : "r"(*(unsigned*)&x));
    return y;
}
__device__ __forceinline__ __half2 u2h2(unsigned u) { return *(__half2*)&u; }
__device__ __forceinline__ void ldsm4(unsigned& r0, unsigned& r1, unsigned& r2, unsigned& r3,
                                      unsigned addr) {
    asm volatile("ldmatrix.sync.aligned.m8n8.x4.shared.b16 {%0,%1,%2,%3}, [%4];\n"
                 : "=r"(r0), "=r"(r1), "=r"(r2), "=r"(r3) : "r"(addr));
}
__device__ __forceinline__ void ldsm4t(unsigned& r0, unsigned& r1, unsigned& r2, unsigned& r3,
                                       unsigned addr) {
    asm volatile("ldmatrix.sync.aligned.m8n8.x4.trans.shared.b16 {%0,%1,%2,%3}, [%4];\n"
                 : "=r"(r0), "=r"(r1), "=r"(r2), "=r"(r3) : "r"(addr));
}
__device__ __forceinline__ void mma_f16(unsigned& c0, unsigned& c1,
                                        unsigned a0, unsigned a1, unsigned a2, unsigned a3,
                                        unsigned b0, unsigned b1) {
    asm volatile("mma.sync.aligned.m16n8k16.row.col.f16.f16.f16.f16 "
                 "{%0,%1},{%2,%3,%4,%5},{%6,%7},{%0,%1};\n"
                 : "+r"(c0), "+r"(c1)
                 : "r"(a0), "r"(a1), "r"(a2), "r"(a3), "r"(b0), "r"(b1));
}

// B tile: 128 rows x 512B -> smem pitch 528 via cp.async
__device__ __forceinline__ void load_tile_b(unsigned dst_base, const char* src, int t) {
#pragma unroll
    for (int i = 0; i < 16; ++i) {
        const int u = i * 256 + t;
        const int row = u >> 5, c16 = u & 31;
        const unsigned dst = dst_base + (unsigned)(row * PITCH + c16 * 16);
        const char* s = src + ((size_t)row * 512 + (size_t)c16 * 16);
        asm volatile("cp.async.cg.shared.global [%0], [%1], 16;" :: "r"(dst), "l"(s) : "memory");
    }
    asm volatile("cp.async.commit_group;" ::: "memory");
}

// ---------------------------------------------------------------------------
// 1) label patch means -> flags
// ---------------------------------------------------------------------------
__global__ void label_kernel(const float* __restrict__ lab) {
    __shared__ float sred[8];
    const int p = blockIdx.x, t = threadIdx.x;
    const int b = p >> 6, j = (p >> 3) & 7, k = p & 7;
    const float* base = lab + (size_t)b * 65536 + (size_t)j * 32 * 256 + k * 32;
    float sum = 0.f;
#pragma unroll
    for (int it = 0; it < 4; ++it) {
        int u = t + 256 * it;
        int y = u >> 5, x = u & 31;
        sum += base[y * 256 + x];
    }
#pragma unroll
    for (int o = 16; o; o >>= 1) sum += __shfl_xor_sync(~0u, sum, o);
    if ((t & 31) == 0) sred[t >> 5] = sum;
    __syncthreads();
    if (t == 0) {
        float s2 = 0.f;
#pragma unroll
        for (int i = 0; i < 8; ++i) s2 += sred[i];
        g_flags[p] = (s2 * (1.f / 1024.f) < 0.1f) ? 1 : 0;
    }
}

// ---------------------------------------------------------------------------
// 2) permutation: sort patches by flag -> slots; pair info per CTA
// ---------------------------------------------------------------------------
__global__ void perm_kernel() {
    __shared__ int sc[512], sflag[512];
    const int t = threadIdx.x;
    const int f = g_flags[t];
    sc[t] = f;
    __syncthreads();
    for (int off = 1; off < 512; off <<= 1) {
        int add = (t >= off) ? sc[t - off] : 0;
        __syncthreads();
        sc[t] += add;
        __syncthreads();
    }
    const int npos = sc[511];
    const int slot = f ? (sc[t] - 1) : (npos + t - sc[t]);
    g_slot[t] = slot;
    sflag[slot] = f;
    __syncthreads();
    if (t < 256) g_pairinfo[t] = sflag[2 * t] | (sflag[2 * t + 1] << 1);
}

// ---------------------------------------------------------------------------
// 3) banks [32,256,8,8] f32 -> [2048,256] fp16
// ---------------------------------------------------------------------------
__global__ void convert_bank_kernel(const float* __restrict__ neg, const float* __restrict__ pos) {
    __shared__ __half sT[256][66];
    const int blk = blockIdx.x, t = threadIdx.x;
    const int bank = blk >> 5, l = blk & 31;
    const float* src = (bank ? pos : neg) + (size_t)l * 16384;
#pragma unroll 4
    for (int it = 0; it < 64; ++it) {
        int u = t + 256 * it;
        int c = u >> 6, s = u & 63;
        sT[c][s] = __float2half(src[c * 64 + s]);
    }
    __syncthreads();
    __half* dst = (bank ? g_posB : g_negB) + (size_t)l * 64 * 256;
    unsigned* dst32 = (unsigned*)dst;
#pragma unroll 4
    for (int it = 0; it < 32; ++it) {
        int u = t + 256 * it;
        int s = u >> 7, cc = u & 127;
        unsigned lo = __half_as_ushort(sT[2 * cc][s]);
        unsigned hi = __half_as_ushort(sT[2 * cc + 1][s]);
        dst32[s * 128 + cc] = (hi << 16) | lo;
    }
}

// ---------------------------------------------------------------------------
// 4) anchors: block = (b, y_global). Coalesced float4 reads; blocked fp16
//    writes into g_A[slot][yin][c][xin]; exact fp32 pos dot.
// ---------------------------------------------------------------------------
__global__ void convert_anchor_kernel(const float* __restrict__ mainp,
                                      const float* __restrict__ emap) {
    __shared__ float sdot[16][65];
    __shared__ int sslot[8];
    const int bid = blockIdx.x, t = threadIdx.x;
    const int b = bid >> 6, y = bid & 63;
    const int j = y >> 3, yin = y & 7;
    if (t < 8) sslot[t] = g_slot[b * 64 + j * 8 + t];
    __syncthreads();

    const int g = t & 15, r = t >> 4;
    const int slot = sslot[g >> 1];
    const unsigned xh = (unsigned)(g & 1);
    const size_t base4 = ((size_t)b * 256 * 64 + y) * 16 + g;   // float4 units, c=0
    const float4* mp = (const float4*)mainp;
    const float4* ep = (const float4*)emap;
    uint2* Aout = (uint2*)g_A;

    float d0 = 0.f, d1 = 0.f, d2 = 0.f, d3 = 0.f;
#pragma unroll
    for (int it = 0; it < 16; ++it) {
        const int c = r + 16 * it;
        const size_t o = base4 + (size_t)c * 1024;
        const float4 mv = mp[o];
        const float4 ev = ep[o];
        d0 += mv.x * ev.x; d1 += mv.y * ev.y; d2 += mv.z * ev.z; d3 += mv.w * ev.w;
        const __half2 lo = __floats2half2_rn(mv.x * SCALEF, mv.y * SCALEF);
        const __half2 hi = __floats2half2_rn(mv.z * SCALEF, mv.w * SCALEF);
        uint2 v;
        v.x = *(const unsigned*)&lo;
        v.y = *(const unsigned*)&hi;
        Aout[(size_t)((slot * 8 + yin) * 256 + c) * 2 + xh] = v;
    }
    sdot[r][4 * g + 0] = d0; sdot[r][4 * g + 1] = d1;
    sdot[r][4 * g + 2] = d2; sdot[r][4 * g + 3] = d3;
    __syncthreads();
    if (t < 64) {
        float dd = 0.f;
#pragma unroll
        for (int i = 0; i < 16; ++i) dd += sdot[i][t];
        g_pos_sim[sslot[t >> 3] * 64 + yin * 8 + (t & 7)] = dd * SCALEF;
    }
}

// ---------------------------------------------------------------------------
// 5) HMMA f16-acc GEMM + online softmax. grid 256, block 256 (8 warps, 4Mx2N).
// ---------------------------------------------------------------------------
#define SMEM_DYN (65536 + 2 * TILEB)

__global__ __launch_bounds__(256, 1) void gemm_hmma_kernel() {
    extern __shared__ __align__(16) unsigned char dsm[];
    __shared__ float sh_m[128], sh_s[128], red[8];

    const int t = threadIdx.x, w = t >> 5, lane = t & 31, q = blockIdx.x;
    const unsigned sA_u = sm2u(dsm);
    const unsigned sB_u[2] = { sA_u + 65536u, sA_u + 65536u + TILEB };

    const int info = g_pairinfo[q];
    const int f0 = info & 1, f1 = (info >> 1) & 1;
    const int mixed = (f0 != f1);
    const int nch = mixed ? 32 : 16;

    const char* negc = (const char*)g_negB;
    const char* posc = (const char*)g_posB;
    auto bsrc = [&](int cc) -> const char* {
        const int f = mixed ? ((cc >> 4) ? f1 : f0) : f0;
        return (f ? posc : negc) + (size_t)(cc & 15) * 65536;
    };

    // preload A (linear 64KB) + B(chunk0)
    {
        const char* Ag = (const char*)g_A + (size_t)q * 65536;
#pragma unroll
        for (int i = 0; i < 16; ++i) {
            const int u = i * 256 + t;
            asm volatile("cp.async.cg.shared.global [%0], [%1], 16;"
                         :: "r"(sA_u + (unsigned)(u * 16)), "l"(Ag + (size_t)u * 16) : "memory");
        }
        asm volatile("cp.async.commit_group;" ::: "memory");
    }
    load_tile_b(sB_u[0], bsrc(0), t);
    asm volatile("cp.async.wait_group 0;" ::: "memory");
    __syncthreads();

    const int mw = w & 3, nw = w >> 2;
    const unsigned a_lane = (unsigned)(((lane >> 3) & 1) * 4096 +
                                       ((lane & 7) + 8 * (lane >> 4)) * 16);
    const unsigned a_base = sA_u + (unsigned)(mw * 16384) + a_lane;
    const unsigned b_off = (unsigned)((nw * 64 + (lane & 7) + 8 * (lane >> 4)) * PITCH +
                                      ((lane >> 3) & 1) * 16);

    float m_st[4] = {NEG_HUGE, NEG_HUGE, NEG_HUGE, NEG_HUGE};
    float s_st[4] = {0.f, 0.f, 0.f, 0.f};

    for (int cc = 0; cc < nch; ++cc) {
        const int buf = cc & 1;
        if (cc + 1 < nch) load_tile_b(sB_u[buf ^ 1], bsrc(cc + 1), t);

        const bool active = !mixed || ((mw >> 1) == (cc >> 4));
        if (active) {
            // acc[f][nt][p][h] : f=row16-tile, nt=col16-tile, p=n8 half, h=row-8 group
            unsigned acc[2][4][2][2];
            const unsigned ZH = 0u;
#pragma unroll
            for (int f = 0; f < 2; ++f)
#pragma unroll
                for (int nt = 0; nt < 4; ++nt)
#pragma unroll
                    for (int p = 0; p < 2; ++p) {
                        acc[f][nt][p][0] = ZH; acc[f][nt][p][1] = ZH;
                    }
            const unsigned bb = sB_u[buf] + b_off;
#pragma unroll
            for (int ks = 0; ks < 16; ++ks) {
                unsigned a[2][4];
                ldsm4t(a[0][0], a[0][1], a[0][2], a[0][3], a_base + (unsigned)(ks * 256));
                ldsm4t(a[1][0], a[1][1], a[1][2], a[1][3],
                       a_base + (unsigned)(8192 + ks * 256));
#pragma unroll
                for (int nt = 0; nt < 4; ++nt) {
                    unsigned b0, b1, b2, b3;
                    ldsm4(b0, b1, b2, b3, bb + (unsigned)(nt * 16 * PITCH + ks * 32));
                    mma_f16(acc[0][nt][0][0], acc[0][nt][0][1],
                            a[0][0], a[0][1], a[0][2], a[0][3], b0, b1);
                    mma_f16(acc[0][nt][1][0], acc[0][nt][1][1],
                            a[0][0], a[0][1], a[0][2], a[0][3], b2, b3);
                    mma_f16(acc[1][nt][0][0], acc[1][nt][0][1],
                            a[1][0], a[1][1], a[1][2], a[1][3], b0, b1);
                    mma_f16(acc[1][nt][1][0], acc[1][nt][1][1],
                            a[1][0], a[1][1], a[1][2], a[1][3], b2, b3);
                }
            }
            // ---- online softmax: 4 row-slots idx=(f,h) ----
#pragma unroll
            for (int idx = 0; idx < 4; ++idx) {
                const int f = idx >> 1, h = idx & 1;
                __half2 mx2 = u2h2(acc[f][0][0][h]);
#pragma unroll
                for (int nt = 0; nt < 4; ++nt)
#pragma unroll
                    for (int p = 0; p < 2; ++p)
                        if (nt || p) mx2 = __hmax2(mx2, u2h2(acc[f][nt][p][h]));
                float mx = fmaxf(__low2float(mx2), __high2float(mx2));
                mx = fmaxf(mx, __shfl_xor_sync(~0u, mx, 1));
                mx = fmaxf(mx, __shfl_xor_sync(~0u, mx, 2));
                const float nm = fmaxf(m_st[idx], mx);
                const __half2 nm2 = __float2half2_rn(nm);
                __half2 s2a = __floats2half2_rn(0.f, 0.f);
                __half2 s2b = __floats2half2_rn(0.f, 0.f);
#pragma unroll
                for (int nt = 0; nt < 4; ++nt) {
                    s2a = __hadd2(s2a, h2ex2(__hsub2(u2h2(acc[f][nt][0][h]), nm2)));
                    s2b = __hadd2(s2b, h2ex2(__hsub2(u2h2(acc[f][nt][1][h]), nm2)));
                }
                const __half2 s2 = __hadd2(s2a, s2b);
                float su = __low2float(s2) + __high2float(s2);
                su += __shfl_xor_sync(~0u, su, 1);
                su += __shfl_xor_sync(~0u, su, 2);
                s_st[idx] = s_st[idx] * ex2f(m_st[idx] - nm) + su;
                m_st[idx] = nm;
            }
        }
        if (cc + 1 < nch) asm volatile("cp.async.wait_group 0;" ::: "memory");
        __syncthreads();
    }

    // ---- combine the two N-half warps per row, then per-row loss ----
    if (nw == 1 && (lane & 3) == 0) {
#pragma unroll
        for (int idx = 0; idx < 4; ++idx) {
            const int row = mw * 32 + (idx >> 1) * 16 + (lane >> 2) + 8 * (idx & 1);
            sh_m[row] = m_st[idx];
            sh_s[row] = s_st[idx];
        }
    }
    __syncthreads();
    float loss = 0.f;
    if (nw == 0 && (lane & 3) == 0) {
#pragma unroll
        for (int idx = 0; idx < 4; ++idx) {
            const int row = mw * 32 + (idx >> 1) * 16 + (lane >> 2) + 8 * (idx & 1);
            const float m2 = sh_m[row], s2 = sh_s[row];
            const float M = fmaxf(m_st[idx], m2);
            const float S = s_st[idx] * ex2f(m_st[idx] - M) + s2 * ex2f(m2 - M);
            const float p = g_pos_sim[q * 128 + row];
            const float mf = fmaxf(M, p);
            const float ep = ex2f(p - mf);
            const float denom = S * ex2f(M - mf) + ep + EPSV;
            loss += -logf(ep / denom + EPSV);
        }
    }
#pragma unroll
    for (int o = 16; o; o >>= 1) loss += __shfl_xor_sync(~0u, loss, o);
    if (lane == 0) red[w] = loss;
    __syncthreads();
    if (t == 0) {
        float tot = 0.f;
#pragma unroll
        for (int i = 0; i < 8; ++i) tot += red[i];
        g_part[q] = tot;
    }
}

// ---------------------------------------------------------------------------
// 6) final reduction
// ---------------------------------------------------------------------------
__global__ void finalize_kernel(float* __restrict__ out) {
    __shared__ float sred[8];
    const int t = threadIdx.x;
    float v = g_part[t];
#pragma unroll
    for (int o = 16; o; o >>= 1) v += __shfl_xor_sync(~0u, v, o);
    if ((t & 31) == 0) sred[t >> 5] = v;
    __syncthreads();
    if (t == 0) {
        float tot = 0.f;
#pragma unroll
        for (int i = 0; i < 8; ++i) tot += sred[i];
        out[0] = tot * (1.f / 32768.f);
    }
}

// ---------------------------------------------------------------------------
extern "C" void kernel_launch(void* const* d_in, const int* in_sizes, int n_in,
                              void* d_out, int out_size) {
    const float* mainp = (const float*)d_in[0];
    const float* emap  = (const float*)d_in[1];
    const float* lab   = (const float*)d_in[2];
    const float* neg   = (const float*)d_in[3];
    const float* pos   = (const float*)d_in[4];
    float* out = (float*)d_out;

    cudaFuncSetAttribute(gemm_hmma_kernel,
                         cudaFuncAttributeMaxDynamicSharedMemorySize, SMEM_DYN);

    label_kernel<<<NPATCH, 256>>>(lab);
    perm_kernel<<<1, 512>>>();
    convert_bank_kernel<<<64, 256>>>(neg, pos);
    convert_anchor_kernel<<<NPATCH, 256>>>(mainp, emap);
    gemm_hmma_kernel<<<256, 256, SMEM_DYN>>>();
    finalize_kernel<<<1, 256>>>(out);
}